// round 2
// baseline (speedup 1.0000x reference)
#include <cuda_runtime.h>
#include <cstdint>
#include <cstddef>

// ---------------- dims ----------------
#define C2_ 32
#define C1_ 64
#define T_  2048
#define AVGF_ 32
#define SEG_ 64
#define M_  2048
#define HA_ 16
#define DH_ 128

// ---------------- scratch (device globals; no allocs allowed) ----------------
__device__ float g_altx[AVGF_ * M_];
__device__ float g_s   [AVGF_ * M_];
__device__ float g_y   [AVGF_ * M_];
__device__ float g_qkv [AVGF_ * 3 * M_];
__device__ float g_imv [AVGF_ * M_];
__device__ float g_s2  [AVGF_ * M_];
__device__ float g_h   [AVGF_ * 4 * M_];
__device__ float g_part[2097152];   // max split-K partials: 8*32*6144 = 1.57M floats

// ---------------- helpers ----------------
__device__ __forceinline__ void cp16(float* sdst, const float* gsrc) {
    uint32_t d = (uint32_t)__cvta_generic_to_shared(sdst);
    asm volatile("cp.async.cg.shared.global [%0], [%1], 16;" :: "r"(d), "l"(gsrc));
}
// 3xTF32 split: hi = f truncated to tf32 (exact tf32 value); lo = f - hi (exact).
// lo's sub-tf32 bits are truncated by the MMA HW -> error ~2^-21 relative. Cheap: 1 LOP3 + 1 FADD.
__device__ __forceinline__ void split_tf32(float f, uint32_t& hi, uint32_t& lo) {
    hi = __float_as_uint(f) & 0xffffe000u;
    lo = __float_as_uint(f - __uint_as_float(hi));
}
__device__ __forceinline__ void mma8(float* c,
    uint32_t a0, uint32_t a1, uint32_t a2, uint32_t a3, uint32_t b0, uint32_t b1) {
    asm volatile(
        "mma.sync.aligned.m16n8k8.row.col.f32.tf32.tf32.f32 "
        "{%0,%1,%2,%3},{%4,%5,%6,%7},{%8,%9},{%0,%1,%2,%3};"
        : "+f"(c[0]), "+f"(c[1]), "+f"(c[2]), "+f"(c[3])
        : "r"(a0), "r"(a1), "r"(a2), "r"(a3), "r"(b0), "r"(b1));
}

// ---------------- prep: segment-mean -> altx [32, 2048] ----------------
__global__ void prep_kernel(const float* __restrict__ x, float* __restrict__ altx) {
    int i = blockIdx.x, c1 = blockIdx.y;
    int t = threadIdx.x;             // 256
    int c2 = t >> 3, l8 = t & 7;
    const float4* p = (const float4*)(x + ((size_t)(c2 * C1_ + c1)) * T_ + i * SEG_ + l8 * 8);
    float4 a = p[0], b = p[1];
    float s = a.x + a.y + a.z + a.w + b.x + b.y + b.z + b.w;
    s += __shfl_down_sync(0xffffffffu, s, 4);
    s += __shfl_down_sync(0xffffffffu, s, 2);
    s += __shfl_down_sync(0xffffffffu, s, 1);
    if (l8 == 0) altx[i * M_ + c1 * C2_ + c2] = s * (1.f / 64.f);
}

// ---------------- GEMM: out[i][n] = sum_k W[n][k] * A[i][k]  (3xTF32 MMA) -----
#define WST 68   // padded smem row stride (floats)
__global__ __launch_bounds__(256) void gemm_tc(
    const float* __restrict__ W, const float* __restrict__ A,
    float* __restrict__ P, int N, int K, int Kc)
{
    extern __shared__ float sm[];
    float* sW = sm;                   // 2 stages * 128*WST
    float* sA = sm + 2 * 128 * WST;   // 2 stages * 32*WST
    const int tid = threadIdx.x;
    const int nbase = blockIdx.x * 128;
    const int kstart = blockIdx.y * Kc;
    const int iters = Kc >> 6;        // KSTEP = 64

    float acc[4][4];
#pragma unroll
    for (int i = 0; i < 4; i++)
#pragma unroll
        for (int j = 0; j < 4; j++) acc[i][j] = 0.f;

    const int w = tid >> 5, lane = tid & 31;
    const int g = lane >> 2, tg = lane & 3;
    const int n0 = w * 16;

    auto load_stage = [&](int st, int k0) {
        float* wd = sW + st * (128 * WST);
        const float* Wg = W + (size_t)nbase * K + k0;
#pragma unroll
        for (int j = 0; j < 8; j++) {
            int c = tid + j * 256;
            int n = c >> 4, q = (c & 15) << 2;
            cp16(wd + n * WST + q, Wg + (size_t)n * K + q);
        }
        float* ad = sA + st * (32 * WST);
        const float* Ag = A + k0;
#pragma unroll
        for (int j = 0; j < 2; j++) {
            int c = tid + j * 256;
            int n = c >> 4, q = (c & 15) << 2;
            cp16(ad + n * WST + q, Ag + (size_t)n * K + q);
        }
    };

    load_stage(0, kstart);
    asm volatile("cp.async.commit_group;" ::: "memory");
    for (int it = 0; it < iters; it++) {
        if (it + 1 < iters) load_stage((it + 1) & 1, kstart + ((it + 1) << 6));
        asm volatile("cp.async.commit_group;" ::: "memory");
        asm volatile("cp.async.wait_group 1;" ::: "memory");
        __syncthreads();
        const float* wbs = sW + (it & 1) * (128 * WST);
        const float* abs_ = sA + (it & 1) * (32 * WST);
#pragma unroll
        for (int k8 = 0; k8 < 8; k8++) {
            const float* ab = abs_ + (k8 << 3);
            float af[8];
            af[0] = ab[g * WST + tg];
            af[1] = ab[(g + 8) * WST + tg];
            af[2] = ab[g * WST + tg + 4];
            af[3] = ab[(g + 8) * WST + tg + 4];
            af[4] = ab[(g + 16) * WST + tg];
            af[5] = ab[(g + 24) * WST + tg];
            af[6] = ab[(g + 16) * WST + tg + 4];
            af[7] = ab[(g + 24) * WST + tg + 4];
            uint32_t ah[8], al[8];
#pragma unroll
            for (int j = 0; j < 8; j++) split_tf32(af[j], ah[j], al[j]);

            const float* wb = wbs + (k8 << 3);
            float bf[4];
            bf[0] = wb[(n0 + g) * WST + tg];
            bf[1] = wb[(n0 + g) * WST + tg + 4];
            bf[2] = wb[(n0 + 8 + g) * WST + tg];
            bf[3] = wb[(n0 + 8 + g) * WST + tg + 4];
            uint32_t bh[4], bl[4];
#pragma unroll
            for (int j = 0; j < 4; j++) split_tf32(bf[j], bh[j], bl[j]);

            // hi * hi
            mma8(acc[0], ah[0], ah[1], ah[2], ah[3], bh[0], bh[1]);
            mma8(acc[1], ah[4], ah[5], ah[6], ah[7], bh[0], bh[1]);
            mma8(acc[2], ah[0], ah[1], ah[2], ah[3], bh[2], bh[3]);
            mma8(acc[3], ah[4], ah[5], ah[6], ah[7], bh[2], bh[3]);
            // lo * hi
            mma8(acc[0], al[0], al[1], al[2], al[3], bh[0], bh[1]);
            mma8(acc[1], al[4], al[5], al[6], al[7], bh[0], bh[1]);
            mma8(acc[2], al[0], al[1], al[2], al[3], bh[2], bh[3]);
            mma8(acc[3], al[4], al[5], al[6], al[7], bh[2], bh[3]);
            // hi * lo
            mma8(acc[0], ah[0], ah[1], ah[2], ah[3], bl[0], bl[1]);
            mma8(acc[1], ah[4], ah[5], ah[6], ah[7], bl[0], bl[1]);
            mma8(acc[2], ah[0], ah[1], ah[2], ah[3], bl[2], bl[3]);
            mma8(acc[3], ah[4], ah[5], ah[6], ah[7], bl[2], bl[3]);
        }
        __syncthreads();
    }
    float* Pb = P + (size_t)(blockIdx.y * 32) * N + nbase;
#pragma unroll
    for (int t4 = 0; t4 < 4; t4++) {
        int r = g + ((t4 & 1) << 4);
        int c = n0 + ((t4 >> 1) << 3) + (tg << 1);
        *(float2*)(Pb + (size_t)r * N + c) = make_float2(acc[t4][0], acc[t4][1]);
        *(float2*)(Pb + (size_t)(r + 8) * N + c) = make_float2(acc[t4][2], acc[t4][3]);
    }
}

// ---------------- reduce split-K partials + fused epilogue ----------------
// modes: 0 = +sin/cos positional bias, 1 = none, 2 = +residual (extra[e]),
//        3 = +bias[n] then exact GELU, 4 = +bias[n]
__global__ void reduce_epi(const float* __restrict__ P, int N, int S, int mode,
                           const float* __restrict__ extra, float* __restrict__ out)
{
    int idx = blockIdx.x * blockDim.x + threadIdx.x;  // over 32*N/4
    int e = idx << 2;
    int i = e / N, n = e - i * N;
    float v[4] = {0.f, 0.f, 0.f, 0.f};
    for (int s = 0; s < S; s++) {
        const float4 p = *(const float4*)(P + (size_t)(s * 32 + i) * N + n);
        v[0] += p.x; v[1] += p.y; v[2] += p.z; v[3] += p.w;
    }
    if (mode == 0) {
#pragma unroll
        for (int c = 0; c < 4; c++) {
            int col = n + c;
            float ang = (float)i * exp2f((float)(col & ~1) * (-13.28771237954945f / 1024.f));
            v[c] += (col & 1) ? cosf(ang) : sinf(ang);
        }
    } else if (mode == 2) {
        const float4 r = *(const float4*)(extra + e);
        v[0] += r.x; v[1] += r.y; v[2] += r.z; v[3] += r.w;
    } else if (mode == 3) {
#pragma unroll
        for (int c = 0; c < 4; c++) {
            float t = v[c] + extra[n + c];
            v[c] = 0.5f * t * (1.f + erff(t * 0.7071067811865475f));
        }
    } else if (mode == 4) {
#pragma unroll
        for (int c = 0; c < 4; c++) v[c] += extra[n + c];
    }
    *(float4*)(out + e) = make_float4(v[0], v[1], v[2], v[3]);
}

// ---------------- LayerNorm over rows of 2048 (optionally +residual=input) ---
__global__ __launch_bounds__(256) void ln_kernel(const float* __restrict__ in,
    const float* __restrict__ gw, const float* __restrict__ bw,
    float* __restrict__ out, int addres)
{
    __shared__ float red[16];
    __shared__ float stats[2];
    int row = blockIdx.x, t = threadIdx.x;
    const float4* ip = (const float4*)(in + (size_t)row * M_);
    float4 v0 = ip[t], v1 = ip[t + 256];
    float s = v0.x + v0.y + v0.z + v0.w + v1.x + v1.y + v1.z + v1.w;
    float q = v0.x * v0.x + v0.y * v0.y + v0.z * v0.z + v0.w * v0.w
            + v1.x * v1.x + v1.y * v1.y + v1.z * v1.z + v1.w * v1.w;
#pragma unroll
    for (int o = 16; o > 0; o >>= 1) {
        s += __shfl_down_sync(0xffffffffu, s, o);
        q += __shfl_down_sync(0xffffffffu, q, o);
    }
    int w = t >> 5, l = t & 31;
    if (l == 0) { red[w] = s; red[8 + w] = q; }
    __syncthreads();
    if (t == 0) {
        float S = 0.f, Q = 0.f;
        for (int k = 0; k < 8; k++) { S += red[k]; Q += red[8 + k]; }
        float mean = S * (1.f / (float)M_);
        float var = Q * (1.f / (float)M_) - mean * mean;
        stats[0] = mean;
        stats[1] = rsqrtf(var + 1e-5f);
    }
    __syncthreads();
    float mean = stats[0], rstd = stats[1];
    const float4* gp = (const float4*)gw;
    const float4* bp = (const float4*)bw;
    float4* op = (float4*)(out + (size_t)row * M_);
    {
        float4 gv = gp[t], bv = bp[t], o;
        o.x = (v0.x - mean) * rstd * gv.x + bv.x;
        o.y = (v0.y - mean) * rstd * gv.y + bv.y;
        o.z = (v0.z - mean) * rstd * gv.z + bv.z;
        o.w = (v0.w - mean) * rstd * gv.w + bv.w;
        if (addres) { o.x += v0.x; o.y += v0.y; o.z += v0.z; o.w += v0.w; }
        op[t] = o;
    }
    {
        float4 gv = gp[t + 256], bv = bp[t + 256], o;
        o.x = (v1.x - mean) * rstd * gv.x + bv.x;
        o.y = (v1.y - mean) * rstd * gv.y + bv.y;
        o.z = (v1.z - mean) * rstd * gv.z + bv.z;
        o.w = (v1.w - mean) * rstd * gv.w + bv.w;
        if (addres) { o.x += v1.x; o.y += v1.y; o.z += v1.z; o.w += v1.w; }
        op[t + 256] = o;
    }
}

// ---------------- scalar attention + cumulative scan ----------------
__global__ void attn_kernel(const float* __restrict__ qkv, float* __restrict__ imv)
{
    int h = blockIdx.x;          // 16
    int d = threadIdx.x;         // 128
    __shared__ float rsa[AVGF_];
    int w = d >> 5, l = d & 31;
    for (int i = w; i < AVGF_; i += 4) {
        const float* q = qkv + (size_t)i * (3 * M_) + h * DH_;
        const float* k = q + M_;
        float p = 0.f;
#pragma unroll
        for (int dd = 0; dd < 4; dd++) p += q[l + dd * 32] * k[l + dd * 32];
#pragma unroll
        for (int o = 16; o > 0; o >>= 1) p += __shfl_down_sync(0xffffffffu, p, o);
        if (l == 0) rsa[i] = p * 0.08838834764831845f;   // 1/sqrt(128)
    }
    __syncthreads();
    float run = 0.f;
#pragma unroll
    for (int i = 0; i < AVGF_; i++) {
        run += rsa[i] * qkv[(size_t)i * (3 * M_) + 2 * M_ + h * DH_ + d];
        imv[(size_t)i * M_ + h * DH_ + d] = run;
    }
}

// ---------------- launch ----------------
extern "C" void kernel_launch(void* const* d_in, const int* in_sizes, int n_in,
                              void* d_out, int out_size)
{
    const float* x      = (const float*)d_in[0];
    const float* weight = (const float*)d_in[1];
    const float* Wqkv   = (const float*)d_in[2];
    const float* Wo     = (const float*)d_in[3];
    const float* ln1_g  = (const float*)d_in[4];
    const float* ln1_b  = (const float*)d_in[5];
    const float* ln2_g  = (const float*)d_in[6];
    const float* ln2_b  = (const float*)d_in[7];
    const float* fc1_w  = (const float*)d_in[8];
    const float* fc1_b  = (const float*)d_in[9];
    const float* fc2_w  = (const float*)d_in[10];
    const float* fc2_b  = (const float*)d_in[11];
    float* out = (float*)d_out;

    const int SMEMSZ = (2 * 128 * WST + 2 * 32 * WST) * (int)sizeof(float);  // 87040 B
    cudaFuncSetAttribute(gemm_tc, cudaFuncAttributeMaxDynamicSharedMemorySize, SMEMSZ);

    float *altx, *sbuf, *ybuf, *qkv, *imv, *s2, *hbuf, *part;
    cudaGetSymbolAddress((void**)&altx, g_altx);
    cudaGetSymbolAddress((void**)&sbuf, g_s);
    cudaGetSymbolAddress((void**)&ybuf, g_y);
    cudaGetSymbolAddress((void**)&qkv,  g_qkv);
    cudaGetSymbolAddress((void**)&imv,  g_imv);
    cudaGetSymbolAddress((void**)&s2,   g_s2);
    cudaGetSymbolAddress((void**)&hbuf, g_h);
    cudaGetSymbolAddress((void**)&part, g_part);

    // altx
    prep_kernel<<<dim3(AVGF_, C1_), 256>>>(x, altx);
    // s = altx @ weight^T + sinusoidal bias
    gemm_tc<<<dim3(16, 16), 256, SMEMSZ>>>(weight, altx, part, 2048, 2048, 128);
    reduce_epi<<<64, 256>>>(part, 2048, 16, 0, nullptr, sbuf);

    for (int a = 0; a < 3; a++) {
        // y = LN1(s)
        ln_kernel<<<32, 256>>>(sbuf, ln1_g, ln1_b, ybuf, 0);
        // qkv = y @ Wqkv[a]^T    [32, 6144]
        gemm_tc<<<dim3(48, 8), 256, SMEMSZ>>>(Wqkv + (size_t)a * 3 * HA_ * DH_ * M_,
                                              ybuf, part, 6144, 2048, 256);
        reduce_epi<<<192, 256>>>(part, 6144, 8, 1, nullptr, qkv);
        // scalar attn + cumsum
        attn_kernel<<<16, 128>>>(qkv, imv);
        // s2 = imv @ Wo[a]^T + s
        gemm_tc<<<dim3(16, 16), 256, SMEMSZ>>>(Wo + (size_t)a * M_ * M_,
                                               imv, part, 2048, 2048, 128);
        reduce_epi<<<64, 256>>>(part, 2048, 16, 2, sbuf, s2);
        // s = LN2(s2) + s2
        ln_kernel<<<32, 256>>>(s2, ln2_g, ln2_b, sbuf, 1);
        // h = gelu(s @ fc1^T + b1)   [32, 8192]
        gemm_tc<<<dim3(64, 4), 256, SMEMSZ>>>(fc1_w, sbuf, part, 8192, 2048, 512);
        reduce_epi<<<256, 256>>>(part, 8192, 4, 3, fc1_b, hbuf);
        // s = h @ fc2^T + b2
        gemm_tc<<<dim3(16, 16), 256, SMEMSZ>>>(fc2_w, hbuf, part, 2048, 8192, 512);
        reduce_epi<<<64, 256>>>(part, 2048, 16, 4, fc2_b, (a == 2) ? out : sbuf);
    }
}